// round 14
// baseline (speedup 1.0000x reference)
#include <cuda_runtime.h>
#include <cstdint>

#define BB 4
#define NQ 4096
#define NC 4096
#define QT 128                 // queries per CTA
#define NKS 256                // k-steps of K=16
#define NTHREADS 512

// weight scale: w' = 2^(t+15); cancels in normalization, epilogue descales density
#define WSCALE_LOG 15.0f
#define WDESCALE 3.0517578125e-05f   // 2^-15

// dynamic smem (bytes)
#define OFF_B    0                     // B frags bf16: [256 ks][32 lanes] uint2 = 64KB
#define OFF_G16  65536                 // per cpair: {2Cx0,2Cx1,2Cy0,2Cy1} = 2048*16 = 32KB
#define OFF_G8   98304                 // [ks][j]: {-n2j,-n2j+1,-n2j+8,-n2j+9} = 1024*16 = 16KB
#define OFF_SCR  114688                // cross-half reduce scratch 8KB
#define SMEM_TOTAL (OFF_SCR + 8192)    // 120KB

static __device__ __forceinline__ uint64_t addx2(uint64_t a, uint64_t b) {
    uint64_t r; asm("add.rn.f32x2 %0, %1, %2;" : "=l"(r) : "l"(a), "l"(b)); return r;
}
static __device__ __forceinline__ uint64_t fmax2(uint64_t a, uint64_t b, uint64_t c) {
    uint64_t r; asm("fma.rn.f32x2 %0, %1, %2, %3;" : "=l"(r) : "l"(a), "l"(b), "l"(c)); return r;
}
static __device__ __forceinline__ uint64_t packf2(float lo, float hi) {
    uint64_t r; asm("mov.b64 %0, {%1, %2};" : "=l"(r) : "f"(lo), "f"(hi)); return r;
}
// bf16x2 pack via cvt (staging only, off the hot loop); low element = lo
static __device__ __forceinline__ uint32_t packb2_cvt(float lo, float hi) {
    uint32_t r; asm("cvt.rn.bf16x2.f32 %0, %1, %2;" : "=r"(r) : "f"(hi), "f"(lo)); return r;
}
// two weights -> bf16x2 A-fragment register, NO F2FP: +0x8000 rounds (alu),
// PRMT extracts the two high halves (alu). XU pipe carries only the 2 ex2.
static __device__ __forceinline__ uint32_t wpair(uint64_t cx2, uint64_t cy2, uint64_t ncc,
                                                 uint64_t Qxx, uint64_t Qyy, uint64_t Qbb) {
    uint64_t tt = addx2(Qbb, ncc);
    tt = fmax2(cx2, Qxx, tt);
    tt = fmax2(cy2, Qyy, tt);
    float lo, hi;
    asm("mov.b64 {%0, %1}, %2;" : "=f"(lo), "=f"(hi) : "l"(tt));
    float w0, w1;
    asm("ex2.approx.ftz.f32 %0, %1;" : "=f"(w0) : "f"(lo));
    asm("ex2.approx.ftz.f32 %0, %1;" : "=f"(w1) : "f"(hi));
    uint32_t u0 = __float_as_uint(w0) + 0x8000u;   // round-to-nearest into bf16
    uint32_t u1 = __float_as_uint(w1) + 0x8000u;
    uint32_t r;
    asm("prmt.b32 %0, %1, %2, 0x7632;" : "=r"(r) : "r"(u0), "r"(u1));
    return r;                                       // {w1.bf16, w0.bf16}
}
static __device__ __forceinline__ void mma16(float& c0, float& c1, float& c2, float& c3,
                                             uint32_t a0, uint32_t a1, uint32_t a2, uint32_t a3,
                                             uint32_t b0, uint32_t b1) {
    asm volatile(
        "mma.sync.aligned.m16n8k16.row.col.f32.bf16.bf16.f32 "
        "{%0,%1,%2,%3}, {%4,%5,%6,%7}, {%8,%9}, {%0,%1,%2,%3};"
        : "+f"(c0), "+f"(c1), "+f"(c2), "+f"(c3)
        : "r"(a0), "r"(a1), "r"(a2), "r"(a3), "r"(b0), "r"(b1));
}

__global__ void __launch_bounds__(NTHREADS, 1)
setconv_h16(const float* __restrict__ xq, const float* __restrict__ xc,
            const float* __restrict__ yc, const float* __restrict__ lls,
            float* __restrict__ out)
{
    extern __shared__ char smem[];
    const int t = threadIdx.x;
    const int wid = t >> 5;
    const int lane = t & 31;

    const int b  = blockIdx.x >> 5;
    const int qt = blockIdx.x & 31;

    // s = sqrt(log2(e)/2)/ls  ->  exp(-d2/(2 ls^2)) = exp2(-|s dx|^2 - |s dy|^2)
    const float s = 0.84932184f * __expf(-lls[0]);

    // ---- stage B fragments (bf16, rounded cvt off the hot loop) ----
    {
        const float* Yb = yc + (size_t)b * NC * 8;
        uint2* Bf = (uint2*)(smem + OFF_B);
        #pragma unroll 4
        for (int e = t; e < NKS * 32; e += NTHREADS) {
            int ks = e >> 5, l = e & 31;
            int c0 = ks * 16 + 2 * (l & 3);
            int n = l >> 2;
            float y00 = Yb[(size_t)c0 * 8 + n];
            float y01 = Yb[(size_t)(c0 + 1) * 8 + n];
            float y10 = Yb[(size_t)(c0 + 8) * 8 + n];
            float y11 = Yb[(size_t)(c0 + 9) * 8 + n];
            Bf[e] = make_uint2(packb2_cvt(y00, y01), packb2_cvt(y10, y11));
        }
    }
    // ---- stage context geometry (pairwise packed, pre-scaled) ----
    {
        const float2* Xb = (const float2*)(xc + (size_t)b * NC * 2);
        float4* G16 = (float4*)(smem + OFF_G16);
        #pragma unroll 4
        for (int p = t; p < NC / 2; p += NTHREADS) {
            float2 p0 = Xb[2 * p], p1 = Xb[2 * p + 1];
            float X0 = p0.x * s, Y0 = p0.y * s;
            float X1 = p1.x * s, Y1 = p1.y * s;
            G16[p] = make_float4(2.f * X0, 2.f * X1, 2.f * Y0, 2.f * Y1);
        }
        // G8x[ks*4+j] = {-n(2j), -n(2j+1), -n(2j+8), -n(2j+9)} — quad's norms in ONE LDS.128
        float4* G8x = (float4*)(smem + OFF_G8);
        const float* Xf = (const float*)Xb;
        #pragma unroll 4
        for (int i = t; i < NC / 4; i += NTHREADS) {
            int ks = i >> 2, j = i & 3;
            int c0 = ks * 16 + 2 * j;
            float x0 = Xf[(c0 + 0) * 2 + 0] * s, y0 = Xf[(c0 + 0) * 2 + 1] * s;
            float x1 = Xf[(c0 + 1) * 2 + 0] * s, y1 = Xf[(c0 + 1) * 2 + 1] * s;
            float x8 = Xf[(c0 + 8) * 2 + 0] * s, y8 = Xf[(c0 + 8) * 2 + 1] * s;
            float x9 = Xf[(c0 + 9) * 2 + 0] * s, y9 = Xf[(c0 + 9) * 2 + 1] * s;
            G8x[i] = make_float4(-fmaf(x0, x0, y0 * y0), -fmaf(x1, x1, y1 * y1),
                                 -fmaf(x8, x8, y8 * y8), -fmaf(x9, x9, y9 * y9));
        }
    }

    // per-thread queries: qa = group row, qb = +8
    const int g = wid & 7;                  // q-group 0..7 (16 queries each)
    const int half = wid >> 3;              // K-half 0/1
    const int qa_loc = g * 16 + (lane >> 2);
    const int qg = qt * QT + qa_loc;
    const float qax = xq[((size_t)b * NQ + qg) * 2 + 0] * s;
    const float qay = xq[((size_t)b * NQ + qg) * 2 + 1] * s;
    const float qbx = xq[((size_t)b * NQ + qg + 8) * 2 + 0] * s;
    const float qby = xq[((size_t)b * NQ + qg + 8) * 2 + 1] * s;
    const uint64_t Qxa = packf2(qax, qax), Qya = packf2(qay, qay);
    const uint64_t Qxb = packf2(qbx, qbx), Qyb = packf2(qby, qby);
    const float ba  = WSCALE_LOG - fmaf(qax, qax, qay * qay);
    const float bbq = WSCALE_LOG - fmaf(qbx, qbx, qby * qby);
    const uint64_t Qba = packf2(ba, ba), Qbb = packf2(bbq, bbq);

    // ones-row B fragment (density column n=0), bf16 1.0 = 0x3F80
    const uint32_t bones = ((lane >> 2) == 0) ? 0x3F803F80u : 0u;

    __syncthreads();

    float c0 = 0.f, c1 = 0.f, c2 = 0.f, c3 = 0.f;   // features
    float e0 = 0.f, e1 = 0.f, e2 = 0.f, e3 = 0.f;   // density

    const ulonglong2* G16p = (const ulonglong2*)(smem + OFF_G16);
    const ulonglong2* G8xp = (const ulonglong2*)(smem + OFF_G8);
    const uint2*      Bf   = (const uint2*)(smem + OFF_B);

    const int kbeg = half * (NKS / 2);
    const int kend = kbeg + (NKS / 2);
    const int j = lane & 3;

    #pragma unroll 8
    for (int ks = kbeg; ks < kend; ks++) {
        const int p0 = ks * 8 + j;
        ulonglong2 ga = G16p[p0];          // {cx2 pair, cy2 pair} contexts 2j,2j+1
        ulonglong2 gb = G16p[p0 + 4];      // contexts 2j+8, 2j+9
        ulonglong2 nn = G8xp[ks * 4 + j];  // {na pair, nb pair} in ONE load
        uint2 bb = Bf[ks * 32 + lane];

        uint32_t a0 = wpair(ga.x, ga.y, nn.x, Qxa, Qya, Qba);
        uint32_t a1 = wpair(ga.x, ga.y, nn.x, Qxb, Qyb, Qbb);
        uint32_t a2 = wpair(gb.x, gb.y, nn.y, Qxa, Qya, Qba);
        uint32_t a3 = wpair(gb.x, gb.y, nn.y, Qxb, Qyb, Qbb);

        mma16(c0, c1, c2, c3, a0, a1, a2, a3, bb.x, bb.y);
        mma16(e0, e1, e2, e3, a0, a1, a2, a3, bones, bones);
    }

    // ---- combine K-halves ----
    float4* scr = (float4*)(smem + OFF_SCR);
    if (half == 1) {
        scr[(g * 32 + lane) * 2 + 0] = make_float4(c0, c1, c2, c3);
        scr[(g * 32 + lane) * 2 + 1] = make_float4(e0, e2, 0.f, 0.f);
    }
    __syncthreads();
    if (half == 0) {
        float4 f = scr[(g * 32 + lane) * 2 + 0];
        float4 e = scr[(g * 32 + lane) * 2 + 1];
        c0 += f.x; c1 += f.y; c2 += f.z; c3 += f.w;
        e0 += e.x; e2 += e.y;

        // density lives on lanes with j==0; broadcast within quad; descale by 2^-15
        float da = __shfl_sync(0xffffffffu, e0, lane & ~3) * WDESCALE;
        float db = __shfl_sync(0xffffffffu, e2, lane & ~3) * WDESCALE;
        float inva = WDESCALE / (da + 1e-8f);
        float invb = WDESCALE / (db + 1e-8f);

        const int f0 = 2 * j;
        float* oa = out + ((size_t)b * NQ + qg) * 9;
        float* ob = oa + 8 * 9;
        oa[f0] = c0 * inva; oa[f0 + 1] = c1 * inva;
        ob[f0] = c2 * invb; ob[f0 + 1] = c3 * invb;
        if (j == 0) { oa[8] = da; ob[8] = db; }
    }
}

extern "C" void kernel_launch(void* const* d_in, const int* in_sizes, int n_in,
                              void* d_out, int out_size) {
    const float* xq  = (const float*)d_in[0];
    const float* xc  = (const float*)d_in[1];
    const float* yc  = (const float*)d_in[2];
    const float* lls = (const float*)d_in[3];
    float* out = (float*)d_out;

    cudaFuncSetAttribute(setconv_h16, cudaFuncAttributeMaxDynamicSharedMemorySize,
                         SMEM_TOTAL);
    setconv_h16<<<BB * (NQ / QT), NTHREADS, SMEM_TOTAL>>>(xq, xc, yc, lls, out);
}

// round 17
// speedup vs baseline: 1.0721x; 1.0721x over previous
#include <cuda_runtime.h>
#include <cstdint>

#define BB 4
#define NQ 4096
#define NC 4096
#define QT 128                 // queries per CTA
#define NKS 256                // k-steps of K=16
#define NTHREADS 512

// weight scale: w' = 2^(t+15); cancels in normalization, epilogue descales density
#define WSCALE_LOG 15.0f
#define WDESCALE 3.0517578125e-05f   // 2^-15

// dynamic smem (bytes)
#define OFF_B    0                     // B frags fp16: [256 ks][32 lanes] uint2 = 64KB
#define OFF_G16  65536                 // per cpair: {2Cx0,2Cx1,2Cy0,2Cy1} = 2048*16 = 32KB
#define OFF_G8   98304                 // per cpair: {-|C0|^2, -|C1|^2}    = 2048*8  = 16KB
#define OFF_SCR  114688                // cross-half reduce scratch 8KB
#define SMEM_TOTAL (OFF_SCR + 8192)    // 120KB

static __device__ __forceinline__ uint64_t addx2(uint64_t a, uint64_t b) {
    uint64_t r; asm("add.rn.f32x2 %0, %1, %2;" : "=l"(r) : "l"(a), "l"(b)); return r;
}
static __device__ __forceinline__ uint64_t fmax2(uint64_t a, uint64_t b, uint64_t c) {
    uint64_t r; asm("fma.rn.f32x2 %0, %1, %2, %3;" : "=l"(r) : "l"(a), "l"(b), "l"(c)); return r;
}
static __device__ __forceinline__ uint64_t packf2(float lo, float hi) {
    uint64_t r; asm("mov.b64 %0, {%1, %2};" : "=l"(r) : "f"(lo), "f"(hi)); return r;
}
static __device__ __forceinline__ uint32_t packh2(float lo, float hi) {
    uint32_t r; asm("cvt.rn.f16x2.f32 %0, %1, %2;" : "=r"(r) : "f"(hi), "f"(lo)); return r;
}
// two weights (one query, one context pair) -> f16x2 A-fragment register.
// t in packed f32x2; exp in FULL f32 (MUFU); +15 bias avoids fp16 subnormals.
// Also accumulates the raw f32 weight pair into dacc (density — replaces the
// second mma entirely).
static __device__ __forceinline__ uint32_t wpair(uint64_t cx2, uint64_t cy2, uint64_t ncc,
                                                 uint64_t Qxx, uint64_t Qyy, uint64_t Qbb,
                                                 uint64_t& dacc) {
    uint64_t tt = addx2(Qbb, ncc);
    tt = fmax2(cx2, Qxx, tt);
    tt = fmax2(cy2, Qyy, tt);
    float lo, hi;
    asm("mov.b64 {%0, %1}, %2;" : "=f"(lo), "=f"(hi) : "l"(tt));
    float w0, w1;
    asm("ex2.approx.ftz.f32 %0, %1;" : "=f"(w0) : "f"(lo));
    asm("ex2.approx.ftz.f32 %0, %1;" : "=f"(w1) : "f"(hi));
    dacc = addx2(dacc, packf2(w0, w1));
    return packh2(w0, w1);
}
static __device__ __forceinline__ void mma16(float& c0, float& c1, float& c2, float& c3,
                                             uint32_t a0, uint32_t a1, uint32_t a2, uint32_t a3,
                                             uint32_t b0, uint32_t b1) {
    asm volatile(
        "mma.sync.aligned.m16n8k16.row.col.f32.f16.f16.f32 "
        "{%0,%1,%2,%3}, {%4,%5,%6,%7}, {%8,%9}, {%0,%1,%2,%3};"
        : "+f"(c0), "+f"(c1), "+f"(c2), "+f"(c3)
        : "r"(a0), "r"(a1), "r"(a2), "r"(a3), "r"(b0), "r"(b1));
}

__global__ void __launch_bounds__(NTHREADS, 1)
setconv_h16(const float* __restrict__ xq, const float* __restrict__ xc,
            const float* __restrict__ yc, const float* __restrict__ lls,
            float* __restrict__ out)
{
    extern __shared__ char smem[];
    const int t = threadIdx.x;
    const int wid = t >> 5;
    const int lane = t & 31;

    const int b  = blockIdx.x >> 5;
    const int qt = blockIdx.x & 31;

    // s = sqrt(log2(e)/2)/ls  ->  exp(-d2/(2 ls^2)) = exp2(-|s dx|^2 - |s dy|^2)
    const float s = 0.84932184f * __expf(-lls[0]);

    // ---- stage B fragments (fp16) ----
    {
        const float* Yb = yc + (size_t)b * NC * 8;
        uint2* Bf = (uint2*)(smem + OFF_B);
        #pragma unroll 4
        for (int e = t; e < NKS * 32; e += NTHREADS) {
            int ks = e >> 5, l = e & 31;
            int c0 = ks * 16 + 2 * (l & 3);
            int n = l >> 2;
            float y00 = Yb[(size_t)c0 * 8 + n];
            float y01 = Yb[(size_t)(c0 + 1) * 8 + n];
            float y10 = Yb[(size_t)(c0 + 8) * 8 + n];
            float y11 = Yb[(size_t)(c0 + 9) * 8 + n];
            Bf[e] = make_uint2(packh2(y00, y01), packh2(y10, y11));
        }
    }
    // ---- stage context geometry (pairwise packed, pre-scaled) ----
    {
        const float2* Xb = (const float2*)(xc + (size_t)b * NC * 2);
        float4* G16 = (float4*)(smem + OFF_G16);
        float2* G8  = (float2*)(smem + OFF_G8);
        #pragma unroll 4
        for (int p = t; p < NC / 2; p += NTHREADS) {
            float2 p0 = Xb[2 * p], p1 = Xb[2 * p + 1];
            float X0 = p0.x * s, Y0 = p0.y * s;
            float X1 = p1.x * s, Y1 = p1.y * s;
            G16[p] = make_float4(2.f * X0, 2.f * X1, 2.f * Y0, 2.f * Y1);
            G8[p]  = make_float2(-fmaf(X0, X0, Y0 * Y0), -fmaf(X1, X1, Y1 * Y1));
        }
    }

    // per-thread queries: qa = group row, qb = +8
    const int g = wid & 7;                  // q-group 0..7 (16 queries each)
    const int half = wid >> 3;              // K-half 0/1
    const int qa_loc = g * 16 + (lane >> 2);
    const int qg = qt * QT + qa_loc;
    const float qax = xq[((size_t)b * NQ + qg) * 2 + 0] * s;
    const float qay = xq[((size_t)b * NQ + qg) * 2 + 1] * s;
    const float qbx = xq[((size_t)b * NQ + qg + 8) * 2 + 0] * s;
    const float qby = xq[((size_t)b * NQ + qg + 8) * 2 + 1] * s;
    const uint64_t Qxa = packf2(qax, qax), Qya = packf2(qay, qay);
    const uint64_t Qxb = packf2(qbx, qbx), Qyb = packf2(qby, qby);
    const float ba  = WSCALE_LOG - fmaf(qax, qax, qay * qay);
    const float bbq = WSCALE_LOG - fmaf(qbx, qbx, qby * qby);
    const uint64_t Qba = packf2(ba, ba), Qbb = packf2(bbq, bbq);

    __syncthreads();

    float c0 = 0.f, c1 = 0.f, c2 = 0.f, c3 = 0.f;   // features
    uint64_t dA = 0, dB = 0;                         // packed f32x2 density accum

    const ulonglong2* G16p = (const ulonglong2*)(smem + OFF_G16);
    const uint64_t*   G8p  = (const uint64_t*)(smem + OFF_G8);
    const uint2*      Bf   = (const uint2*)(smem + OFF_B);

    const int kbeg = half * (NKS / 2);
    const int kend = kbeg + (NKS / 2);
    const int j = lane & 3;

    #pragma unroll 8
    for (int ks = kbeg; ks < kend; ks++) {
        const int p0 = ks * 8 + j;
        ulonglong2 ga = G16p[p0];          // {cx2 pair, cy2 pair} contexts 2j,2j+1
        uint64_t   na = G8p[p0];
        ulonglong2 gb = G16p[p0 + 4];      // contexts 2j+8, 2j+9
        uint64_t   nb = G8p[p0 + 4];
        uint2 bb = Bf[ks * 32 + lane];

        uint32_t a0 = wpair(ga.x, ga.y, na, Qxa, Qya, Qba, dA);
        uint32_t a1 = wpair(ga.x, ga.y, na, Qxb, Qyb, Qbb, dB);
        uint32_t a2 = wpair(gb.x, gb.y, nb, Qxa, Qya, Qba, dA);
        uint32_t a3 = wpair(gb.x, gb.y, nb, Qxb, Qyb, Qbb, dB);

        mma16(c0, c1, c2, c3, a0, a1, a2, a3, bb.x, bb.y);
    }

    // per-thread density partials (this thread's 4 contexts per kstep)
    float dal, dah, dbl, dbh;
    asm("mov.b64 {%0, %1}, %2;" : "=f"(dal), "=f"(dah) : "l"(dA));
    asm("mov.b64 {%0, %1}, %2;" : "=f"(dbl), "=f"(dbh) : "l"(dB));
    float da = dal + dah;
    float db = dbl + dbh;

    // ---- combine K-halves ----
    float4* scr = (float4*)(smem + OFF_SCR);
    if (half == 1) {
        scr[(g * 32 + lane) * 2 + 0] = make_float4(c0, c1, c2, c3);
        scr[(g * 32 + lane) * 2 + 1] = make_float4(da, db, 0.f, 0.f);
    }
    __syncthreads();
    if (half == 0) {
        float4 f = scr[(g * 32 + lane) * 2 + 0];
        float4 e = scr[(g * 32 + lane) * 2 + 1];
        c0 += f.x; c1 += f.y; c2 += f.z; c3 += f.w;
        da += e.x; db += e.y;

        // quad reduce: all 4 lanes of the quad get the full 16-context sum
        da += __shfl_xor_sync(0xffffffffu, da, 1);
        da += __shfl_xor_sync(0xffffffffu, da, 2);
        db += __shfl_xor_sync(0xffffffffu, db, 1);
        db += __shfl_xor_sync(0xffffffffu, db, 2);

        da *= WDESCALE;                    // back to true density
        db *= WDESCALE;
        float inva = WDESCALE / (da + 1e-8f);
        float invb = WDESCALE / (db + 1e-8f);

        const int f0 = 2 * j;
        float* oa = out + ((size_t)b * NQ + qg) * 9;
        float* ob = oa + 8 * 9;
        oa[f0] = c0 * inva; oa[f0 + 1] = c1 * inva;
        ob[f0] = c2 * invb; ob[f0 + 1] = c3 * invb;
        if (j == 0) { oa[8] = da; ob[8] = db; }
    }
}

extern "C" void kernel_launch(void* const* d_in, const int* in_sizes, int n_in,
                              void* d_out, int out_size) {
    const float* xq  = (const float*)d_in[0];
    const float* xc  = (const float*)d_in[1];
    const float* yc  = (const float*)d_in[2];
    const float* lls = (const float*)d_in[3];
    float* out = (float*)d_out;

    cudaFuncSetAttribute(setconv_h16, cudaFuncAttributeMaxDynamicSharedMemorySize,
                         SMEM_TOTAL);
    setconv_h16<<<BB * (NQ / QT), NTHREADS, SMEM_TOTAL>>>(xq, xc, yc, lls, out);
}